// round 1
// baseline (speedup 1.0000x reference)
#include <cuda_runtime.h>
#include <math.h>

// ---------------- problem constants ----------------
#define N_TOK 16384      // 16*32*32 tokens
#define KCB   16384      // codebook size
#define DDIM  256        // code dim
#define NBATCH 16
#define HWD   1024       // 32*32

// output layout (concatenated reference tuple, fp32)
#define O_OUT   0
#define O_SCAL  4194304          // loss, qerr, util, perp
#define O_WNEW  4194308
#define O_CNEW  (4194308 + 4194304)          // 8388612
#define O_EANEW (8388612 + 16384)            // 8404996

// ---------------- device scratch (no allocs allowed) ----------------
__device__ float g_zT[DDIM * N_TOK];   // [d][n]
__device__ float g_zf[N_TOK * DDIM];   // [n][d]
__device__ float g_wT[DDIM * KCB];     // [d][k]
__device__ float g_wsq[KCB];
__device__ float g_zsq[N_TOK];
__device__ int   g_token[N_TOK];
__device__ float g_counts[KCB];
__device__ float g_esum[KCB * DDIM];
__device__ float g_scal[8];            // 0:S 1:n_sum 2:sumc 3:util_cnt 4:entropy

// ---------------- small helpers ----------------
__device__ __forceinline__ unsigned long long pack2(float x, float y) {
    unsigned long long r;
    asm("mov.b64 %0, {%1, %2};" : "=l"(r) : "f"(x), "f"(y));
    return r;
}
__device__ __forceinline__ void unpack2(unsigned long long v, float& x, float& y) {
    asm("mov.b64 {%0, %1}, %2;" : "=f"(x), "=f"(y) : "l"(v));
}
#define FMA2(acc, a, b) asm("fma.rn.f32x2 %0, %1, %2, %0;" : "+l"(acc) : "l"(a), "l"(b))

__device__ __forceinline__ void cp_async16(void* smem_dst, const void* gsrc) {
    unsigned sa = (unsigned)__cvta_generic_to_shared(smem_dst);
    asm volatile("cp.async.cg.shared.global [%0], [%1], 16;" :: "r"(sa), "l"(gsrc));
}
#define CP_COMMIT() asm volatile("cp.async.commit_group;")
#define CP_WAIT(n)  asm volatile("cp.async.wait_group %0;" :: "n"(n))

__device__ __forceinline__ float blockReduceSum(float v) {
    __shared__ float red[32];
    int lane = threadIdx.x & 31, wid = threadIdx.x >> 5;
    #pragma unroll
    for (int o = 16; o > 0; o >>= 1) v += __shfl_down_sync(0xffffffffu, v, o);
    if (lane == 0) red[wid] = v;
    __syncthreads();
    if (wid == 0) {
        v = (lane < ((blockDim.x + 31) >> 5)) ? red[lane] : 0.f;
        #pragma unroll
        for (int o = 16; o > 0; o >>= 1) v += __shfl_down_sync(0xffffffffu, v, o);
    }
    return v;   // valid on thread 0
}

// ---------------- prep kernels ----------------
__global__ void k_zero() {
    int i = blockIdx.x * blockDim.x + threadIdx.x;
    if (i < KCB * DDIM) g_esum[i] = 0.f;
    if (i < KCB) g_counts[i] = 0.f;
    if (i < 8) g_scal[i] = 0.f;
}

// zT[d][b*1024+p] = z[b][d][p]   (coalesced both sides)
__global__ void k_zT(const float* __restrict__ z) {
    int b = blockIdx.x, d = blockIdx.y;
    const float* src = z + (b * DDIM + d) * HWD;
    float* dst = g_zT + d * N_TOK + b * HWD;
    for (int p = threadIdx.x; p < HWD; p += blockDim.x) dst[p] = src[p];
}

// zf[b*1024+p][d] = z[b][d][p]   (tiled transpose per batch)
__global__ void k_zf(const float* __restrict__ z) {
    __shared__ float t[32][33];
    int b = blockIdx.z;
    int c0 = blockIdx.x * 32;   // p
    int r0 = blockIdx.y * 32;   // d
    const float* src = z + b * DDIM * HWD;
    for (int i = threadIdx.y; i < 32; i += 8)
        t[i][threadIdx.x] = src[(r0 + i) * HWD + c0 + threadIdx.x];
    __syncthreads();
    float* dst = g_zf + b * HWD * DDIM;
    for (int i = threadIdx.y; i < 32; i += 8)
        dst[(c0 + i) * DDIM + r0 + threadIdx.x] = t[threadIdx.x][i];
}

// wT[d][k] = weight[k][d]
__global__ void k_wT(const float* __restrict__ w) {
    __shared__ float t[32][33];
    int c0 = blockIdx.x * 32;   // d
    int r0 = blockIdx.y * 32;   // k
    for (int i = threadIdx.y; i < 32; i += 8)
        t[i][threadIdx.x] = w[(r0 + i) * DDIM + c0 + threadIdx.x];
    __syncthreads();
    for (int i = threadIdx.y; i < 32; i += 8)
        g_wT[(c0 + i) * KCB + r0 + threadIdx.x] = t[threadIdx.x][i];
}

__global__ void k_zsq() {
    int r = blockIdx.x;
    float v = g_zf[r * DDIM + threadIdx.x];
    v *= v;
    v = blockReduceSum(v);
    if (threadIdx.x == 0) g_zsq[r] = v;
}
__global__ void k_wsq(const float* __restrict__ w) {
    int r = blockIdx.x;
    float v = w[r * DDIM + threadIdx.x];
    v *= v;
    v = blockReduceSum(v);
    if (threadIdx.x == 0) g_wsq[r] = v;
}

// ---------------- fused distance GEMM + argmin ----------------
#define TM 64
#define TN 128
#define DK 32
#define GEMM_SMEM ((DDIM * TM + 2 * DK * TN) * 4)   // 96 KB

__global__ void __launch_bounds__(256, 2) k_gemm() {
    extern __shared__ float sm[];
    float* zs = sm;                  // [256][64]  z tile, d-major
    float* ws = sm + DDIM * TM;      // [2][32][128] w chunk double buffer

    int tid = threadIdx.x;
    int tn = tid & 15;               // owns 8 codes
    int tm = tid >> 4;               // owns 4 tokens
    int gm0 = blockIdx.x * TM;

    // load z tile (once)
    for (int j = tid; j < DDIM * (TM / 4); j += 256) {
        int d = j >> 4, c4 = (j & 15) << 2;
        *(float4*)(zs + d * TM + c4) = *(const float4*)(g_zT + d * N_TOK + gm0 + c4);
    }
    float zq[4];
    #pragma unroll
    for (int i = 0; i < 4; i++) zq[i] = g_zsq[gm0 + tm * 4 + i];
    __syncthreads();

    float bestV[4];
    int bestI[4];
    #pragma unroll
    for (int i = 0; i < 4; i++) { bestV[i] = __int_as_float(0x7f800000); bestI[i] = 0; }

    for (int kb = 0; kb < KCB; kb += TN) {
        unsigned long long acc[4][4];
        #pragma unroll
        for (int i = 0; i < 4; i++)
            #pragma unroll
            for (int j = 0; j < 4; j++) acc[i][j] = 0ull;

        // prologue: issue chunk 0
        {
            const float* src = g_wT + kb;
            #pragma unroll
            for (int q = 0; q < 4; q++) {
                int j = tid + q * 256;
                int d = j >> 5, c4 = (j & 31) << 2;
                cp_async16(ws + d * TN + c4, src + d * KCB + c4);
            }
            CP_COMMIT();
        }

        for (int ch = 0; ch < 8; ch++) {
            if (ch < 7) {
                const float* src = g_wT + (ch + 1) * DK * KCB + kb;
                float* dstbuf = ws + ((ch + 1) & 1) * DK * TN;
                #pragma unroll
                for (int q = 0; q < 4; q++) {
                    int j = tid + q * 256;
                    int d = j >> 5, c4 = (j & 31) << 2;
                    cp_async16(dstbuf + d * TN + c4, src + d * KCB + c4);
                }
                CP_COMMIT();
                CP_WAIT(1);
            } else {
                CP_WAIT(0);
            }
            __syncthreads();

            const float* wb = ws + (ch & 1) * DK * TN;
            const float* zb = zs + ch * DK * TM;
            #pragma unroll
            for (int d = 0; d < DK; d++) {
                float4 a = *(const float4*)(zb + d * TM + tm * 4);
                unsigned long long a2[4];
                a2[0] = pack2(a.x, a.x); a2[1] = pack2(a.y, a.y);
                a2[2] = pack2(a.z, a.z); a2[3] = pack2(a.w, a.w);
                ulonglong2 b01 = *(const ulonglong2*)(wb + d * TN + tn * 8);
                ulonglong2 b23 = *(const ulonglong2*)(wb + d * TN + tn * 8 + 4);
                unsigned long long b2a[4] = { b01.x, b01.y, b23.x, b23.y };
                #pragma unroll
                for (int i = 0; i < 4; i++)
                    #pragma unroll
                    for (int j2 = 0; j2 < 4; j2++)
                        FMA2(acc[i][j2], a2[i], b2a[j2]);
            }
            __syncthreads();
        }

        // epilogue: d = fl(fl(zsq + wsq) - 2*dot), running argmin (strict <, ascending k)
        #pragma unroll
        for (int j2 = 0; j2 < 4; j2++) {
            int k0 = kb + tn * 8 + j2 * 2;
            float w0 = __ldg(g_wsq + k0), w1 = __ldg(g_wsq + k0 + 1);
            #pragma unroll
            for (int i = 0; i < 4; i++) {
                float s0, s1;
                unpack2(acc[i][j2], s0, s1);
                float v0 = __fsub_rn(__fadd_rn(zq[i], w0), 2.0f * s0);
                float v1 = __fsub_rn(__fadd_rn(zq[i], w1), 2.0f * s1);
                if (v0 < bestV[i]) { bestV[i] = v0; bestI[i] = k0; }
                if (v1 < bestV[i]) { bestV[i] = v1; bestI[i] = k0 + 1; }
            }
        }
    }

    // cross-thread (over tn) lexicographic reduce: min value, lowest index on ties
    __syncthreads();
    float* rv = sm;
    int* ri = (int*)(sm + 1024);
    #pragma unroll
    for (int i = 0; i < 4; i++) { rv[tid * 4 + i] = bestV[i]; ri[tid * 4 + i] = bestI[i]; }
    __syncthreads();
    if (tn == 0) {
        #pragma unroll
        for (int i = 0; i < 4; i++) {
            float bv = rv[(tm * 16) * 4 + i];
            int bi = ri[(tm * 16) * 4 + i];
            for (int t = 1; t < 16; t++) {
                float v = rv[(tm * 16 + t) * 4 + i];
                int id = ri[(tm * 16 + t) * 4 + i];
                if (v < bv || (v == bv && id < bi)) { bv = v; bi = id; }
            }
            g_token[gm0 + tm * 4 + i] = bi;
        }
    }
}

// ---------------- EMA / stats / output kernels ----------------
__global__ void k_scatter() {
    int n = blockIdx.x;
    int t = g_token[n];
    if (threadIdx.x == 0) atomicAdd(&g_counts[t], 1.0f);
    const float* src = g_zf + n * DDIM;
    float* dst = g_esum + t * DDIM;
    for (int d = threadIdx.x; d < DDIM; d += blockDim.x)
        atomicAdd(&dst[d], src[d]);
}

__global__ void k_cluster(const float* __restrict__ cs, float* __restrict__ ocn) {
    int k = blockIdx.x * 256 + threadIdx.x;
    float cnt = g_counts[k];
    float cn = 0.8f * cs[k] + 0.2f * cnt;
    ocn[k] = cn;
    float nz = (cnt > 0.f) ? 1.f : 0.f;
    float s_cn = cn, s_cnt = cnt, s_nz = nz;
    #pragma unroll
    for (int o = 16; o > 0; o >>= 1) {
        s_cn  += __shfl_down_sync(0xffffffffu, s_cn, o);
        s_cnt += __shfl_down_sync(0xffffffffu, s_cnt, o);
        s_nz  += __shfl_down_sync(0xffffffffu, s_nz, o);
    }
    if ((threadIdx.x & 31) == 0) {
        atomicAdd(&g_scal[1], s_cn);
        atomicAdd(&g_scal[2], s_cnt);
        atomicAdd(&g_scal[3], s_nz);
    }
}

__global__ void k_ema(const float* __restrict__ ea, float* __restrict__ oea) {
    int i = blockIdx.x * 256 + threadIdx.x;
    oea[i] = 0.8f * ea[i] + 0.2f * g_esum[i];
}

__global__ void k_entropy() {
    int k = blockIdx.x * 256 + threadIdx.x;
    float cnt = g_counts[k];
    float sumc = g_scal[2];
    float p = cnt / sumc;
    float term = p * logf(p + 1e-10f);
    #pragma unroll
    for (int o = 16; o > 0; o >>= 1) term += __shfl_down_sync(0xffffffffu, term, o);
    if ((threadIdx.x & 31) == 0) atomicAdd(&g_scal[4], term);
}

__global__ void k_weight(const float* __restrict__ ocn, const float* __restrict__ oea,
                         float* __restrict__ ow) {
    int i = blockIdx.x * 256 + threadIdx.x;
    int k = i >> 8;
    float cn = ocn[k];
    float n = g_scal[1];
    float t = (cn + 1e-5f) / (n + 0.16384f);   // K*EPS = 16384*1e-5
    float smv = t * n;
    ow[i] = oea[i] / smv;
}

__global__ void k_outloss(const float* __restrict__ z, const float* __restrict__ w,
                          float* __restrict__ oout) {
    int idx = blockIdx.x * 256 + threadIdx.x;
    int b = idx >> 18;
    int c = (idx >> 10) & 255;
    int p = idx & 1023;
    int n = (b << 10) | p;
    float zt = z[idx];
    float zqv = __ldg(&w[g_token[n] * DDIM + c]);
    float diff = __fsub_rn(zqv, zt);            // replicate (z_q - zt) rounding
    oout[idx] = __fadd_rn(zt, diff);            // replicate STE rounding exactly
    float sq = diff * diff;
    sq = blockReduceSum(sq);
    if (threadIdx.x == 0) atomicAdd(&g_scal[0], sq);
}

__global__ void k_scalars(float* __restrict__ o) {
    float S = g_scal[0];
    o[0] = 0.25f * (S / 4194304.0f);    // loss = BETA * mean
    o[1] = S / 16384.0f;                // quant_error = mean over tokens of per-token sums
    o[2] = g_scal[3] / 16384.0f;        // utilization
    o[3] = expf(-g_scal[4]);            // perplexity
}

// ---------------- launch ----------------
extern "C" void kernel_launch(void* const* d_in, const int* in_sizes, int n_in,
                              void* d_out, int out_size) {
    const float* z  = (const float*)d_in[0];   // [16,256,32,32]
    const float* w  = (const float*)d_in[1];   // [16384,256]
    const float* cs = (const float*)d_in[2];   // [16384]
    const float* ea = (const float*)d_in[3];   // [16384,256]
    float* out = (float*)d_out;

    float* o_out  = out + O_OUT;
    float* o_scal = out + O_SCAL;
    float* o_wnew = out + O_WNEW;
    float* o_cnew = out + O_CNEW;
    float* o_ea   = out + O_EANEW;

    static bool attr_set = false;
    // idempotent; harmless to call every launch (host-side, not a stream op)
    cudaFuncSetAttribute(k_gemm, cudaFuncAttributeMaxDynamicSharedMemorySize, GEMM_SMEM);
    (void)attr_set;

    k_zero<<<(KCB * DDIM + 255) / 256, 256>>>();
    k_zT<<<dim3(NBATCH, DDIM), 256>>>(z);
    k_zf<<<dim3(32, 8, NBATCH), dim3(32, 8)>>>(z);
    k_wT<<<dim3(8, 512), dim3(32, 8)>>>(w);
    k_zsq<<<N_TOK, 256>>>();
    k_wsq<<<KCB, 256>>>(w);
    k_gemm<<<N_TOK / TM, 256, GEMM_SMEM>>>();
    k_scatter<<<N_TOK, 128>>>();
    k_cluster<<<KCB / 256, 256>>>(cs, o_cnew);
    k_ema<<<(KCB * DDIM) / 256, 256>>>(ea, o_ea);
    k_entropy<<<KCB / 256, 256>>>();
    k_weight<<<(KCB * DDIM) / 256, 256>>>(o_cnew, o_ea, o_wnew);
    k_outloss<<<(NBATCH * DDIM * HWD) / 256, 256>>>(z, w, o_out);
    k_scalars<<<1, 1>>>(o_scal);
}

// round 2
// speedup vs baseline: 1.4760x; 1.4760x over previous
#include <cuda_runtime.h>
#include <math.h>

// ---------------- problem constants ----------------
#define N_TOK 16384      // 16*32*32 tokens
#define KCB   16384      // codebook size
#define DDIM  256        // code dim
#define NBATCH 16
#define HWD   1024       // 32*32

// output layout (concatenated reference tuple, fp32)
#define O_OUT   0
#define O_SCAL  4194304          // loss, qerr, util, perp
#define O_WNEW  4194308
#define O_CNEW  (4194308 + 4194304)          // 8388612
#define O_EANEW (8388612 + 16384)            // 8404996

// ---------------- device scratch (no allocs allowed) ----------------
__device__ float g_zT[DDIM * N_TOK];   // [d][n]
__device__ float g_zf[N_TOK * DDIM];   // [n][d]
__device__ float g_wT[DDIM * KCB];     // [d][k]
__device__ float g_wsq[KCB];
__device__ float g_zsq[N_TOK];
__device__ int   g_token[N_TOK];
__device__ float g_counts[KCB];
__device__ float g_esum[KCB * DDIM];
__device__ float g_scal[8];            // 0:S 1:n_sum 2:sumc 3:util_cnt 4:entropy

// ---------------- small helpers ----------------
__device__ __forceinline__ unsigned long long pack2(float x, float y) {
    unsigned long long r;
    asm("mov.b64 %0, {%1, %2};" : "=l"(r) : "f"(x), "f"(y));
    return r;
}
__device__ __forceinline__ void unpack2(unsigned long long v, float& x, float& y) {
    asm("mov.b64 {%0, %1}, %2;" : "=f"(x), "=f"(y) : "l"(v));
}
#define FMA2(acc, a, b) asm("fma.rn.f32x2 %0, %1, %2, %0;" : "+l"(acc) : "l"(a), "l"(b))

__device__ __forceinline__ void cp_async16(void* smem_dst, const void* gsrc) {
    unsigned sa = (unsigned)__cvta_generic_to_shared(smem_dst);
    asm volatile("cp.async.cg.shared.global [%0], [%1], 16;" :: "r"(sa), "l"(gsrc));
}
#define CP_COMMIT() asm volatile("cp.async.commit_group;")
#define CP_WAIT(n)  asm volatile("cp.async.wait_group %0;" :: "n"(n))

__device__ __forceinline__ float blockReduceSum(float v) {
    __shared__ float red[32];
    int lane = threadIdx.x & 31, wid = threadIdx.x >> 5;
    #pragma unroll
    for (int o = 16; o > 0; o >>= 1) v += __shfl_down_sync(0xffffffffu, v, o);
    if (lane == 0) red[wid] = v;
    __syncthreads();
    if (wid == 0) {
        v = (lane < ((blockDim.x + 31) >> 5)) ? red[lane] : 0.f;
        #pragma unroll
        for (int o = 16; o > 0; o >>= 1) v += __shfl_down_sync(0xffffffffu, v, o);
    }
    return v;   // valid on thread 0
}

// ---------------- prep kernels ----------------
__global__ void k_zero() {
    int i = blockIdx.x * blockDim.x + threadIdx.x;
    if (i < KCB * DDIM) g_esum[i] = 0.f;
    if (i < KCB) g_counts[i] = 0.f;
    if (i < 8) g_scal[i] = 0.f;
}

// zT[d][b*1024+p] = z[b][d][p]   (coalesced both sides)
__global__ void k_zT(const float* __restrict__ z) {
    int b = blockIdx.x, d = blockIdx.y;
    const float* src = z + (b * DDIM + d) * HWD;
    float* dst = g_zT + d * N_TOK + b * HWD;
    for (int p = threadIdx.x; p < HWD; p += blockDim.x) dst[p] = src[p];
}

// zf[b*1024+p][d] = z[b][d][p]   (tiled transpose per batch)
__global__ void k_zf(const float* __restrict__ z) {
    __shared__ float t[32][33];
    int b = blockIdx.z;
    int c0 = blockIdx.x * 32;   // p
    int r0 = blockIdx.y * 32;   // d
    const float* src = z + b * DDIM * HWD;
    for (int i = threadIdx.y; i < 32; i += 8)
        t[i][threadIdx.x] = src[(r0 + i) * HWD + c0 + threadIdx.x];
    __syncthreads();
    float* dst = g_zf + b * HWD * DDIM;
    for (int i = threadIdx.y; i < 32; i += 8)
        dst[(c0 + i) * DDIM + r0 + threadIdx.x] = t[threadIdx.x][i];
}

// wT[d][k] = weight[k][d]
__global__ void k_wT(const float* __restrict__ w) {
    __shared__ float t[32][33];
    int c0 = blockIdx.x * 32;   // d
    int r0 = blockIdx.y * 32;   // k
    for (int i = threadIdx.y; i < 32; i += 8)
        t[i][threadIdx.x] = w[(r0 + i) * DDIM + c0 + threadIdx.x];
    __syncthreads();
    for (int i = threadIdx.y; i < 32; i += 8)
        g_wT[(c0 + i) * KCB + r0 + threadIdx.x] = t[threadIdx.x][i];
}

__global__ void k_zsq() {
    int r = blockIdx.x;
    float v = g_zf[r * DDIM + threadIdx.x];
    v *= v;
    v = blockReduceSum(v);
    if (threadIdx.x == 0) g_zsq[r] = v;
}
__global__ void k_wsq(const float* __restrict__ w) {
    int r = blockIdx.x;
    float v = w[r * DDIM + threadIdx.x];
    v *= v;
    v = blockReduceSum(v);
    if (threadIdx.x == 0) g_wsq[r] = v;
}

// ---------------- fused distance GEMM + argmin ----------------
// CTA: 128 tokens x 128 codes, 256 threads as 16x16, 8x8 per thread.
// z tile [256][128] resident (128KB); w streamed in 64-deep chunks, double buffered.
#define TM 128
#define TN 128
#define DK 64
#define NCH (DDIM / DK)
#define GEMM_SMEM ((DDIM * TM + 2 * DK * TN) * 4)   // 192 KB

__global__ void __launch_bounds__(256, 1) k_gemm() {
    extern __shared__ float sm[];
    float* zs = sm;                  // [256][128]  z tile, d-major
    float* ws = sm + DDIM * TM;      // [2][64][128] w chunk double buffer

    int tid = threadIdx.x;
    int tn = tid & 15;               // owns 8 codes (tn*8 .. tn*8+7)
    int tm = tid >> 4;               // owns 8 tokens (tm*8 .. tm*8+7)
    int gm0 = blockIdx.x * TM;

    // load z tile (once per CTA): 256 rows x 128 tokens
    for (int j = tid; j < DDIM * (TM / 4); j += 256) {
        int d = j >> 5, c4 = (j & 31) << 2;
        *(float4*)(zs + d * TM + c4) = *(const float4*)(g_zT + d * N_TOK + gm0 + c4);
    }
    float zq[8];
    #pragma unroll
    for (int i = 0; i < 8; i++) zq[i] = g_zsq[gm0 + tm * 8 + i];
    __syncthreads();

    float bestV[8];
    int bestI[8];
    #pragma unroll
    for (int i = 0; i < 8; i++) { bestV[i] = __int_as_float(0x7f800000); bestI[i] = 0; }

    for (int kb = 0; kb < KCB; kb += TN) {
        unsigned long long acc[8][4];
        #pragma unroll
        for (int i = 0; i < 8; i++)
            #pragma unroll
            for (int j = 0; j < 4; j++) acc[i][j] = 0ull;

        // prologue: issue chunk 0 (64 rows x 128 codes = 8 float4 per thread)
        {
            const float* src = g_wT + kb;
            #pragma unroll
            for (int q = 0; q < 8; q++) {
                int j = tid + q * 256;
                int d = j >> 5, c4 = (j & 31) << 2;
                cp_async16(ws + d * TN + c4, src + d * KCB + c4);
            }
            CP_COMMIT();
        }

        #pragma unroll 1
        for (int ch = 0; ch < NCH; ch++) {
            if (ch < NCH - 1) {
                const float* src = g_wT + (ch + 1) * DK * KCB + kb;
                float* dstbuf = ws + ((ch + 1) & 1) * DK * TN;
                #pragma unroll
                for (int q = 0; q < 8; q++) {
                    int j = tid + q * 256;
                    int d = j >> 5, c4 = (j & 31) << 2;
                    cp_async16(dstbuf + d * TN + c4, src + d * KCB + c4);
                }
                CP_COMMIT();
                CP_WAIT(1);
            } else {
                CP_WAIT(0);
            }
            __syncthreads();

            const float* wb = ws + (ch & 1) * DK * TN;
            const float* zb = zs + ch * DK * TM;
            #pragma unroll 2
            for (int d = 0; d < DK; d++) {
                float4 a0 = *(const float4*)(zb + d * TM + tm * 8);
                float4 a1 = *(const float4*)(zb + d * TM + tm * 8 + 4);
                unsigned long long a2[8];
                a2[0] = pack2(a0.x, a0.x); a2[1] = pack2(a0.y, a0.y);
                a2[2] = pack2(a0.z, a0.z); a2[3] = pack2(a0.w, a0.w);
                a2[4] = pack2(a1.x, a1.x); a2[5] = pack2(a1.y, a1.y);
                a2[6] = pack2(a1.z, a1.z); a2[7] = pack2(a1.w, a1.w);
                ulonglong2 b01 = *(const ulonglong2*)(wb + d * TN + tn * 8);
                ulonglong2 b23 = *(const ulonglong2*)(wb + d * TN + tn * 8 + 4);
                unsigned long long b2a[4] = { b01.x, b01.y, b23.x, b23.y };
                #pragma unroll
                for (int i = 0; i < 8; i++)
                    #pragma unroll
                    for (int j2 = 0; j2 < 4; j2++)
                        FMA2(acc[i][j2], a2[i], b2a[j2]);
            }
            __syncthreads();
        }

        // epilogue: d = fl(fl(zsq + wsq) - 2*dot), running argmin (strict <, ascending k)
        #pragma unroll
        for (int j2 = 0; j2 < 4; j2++) {
            int k0 = kb + tn * 8 + j2 * 2;
            float w0 = __ldg(g_wsq + k0), w1 = __ldg(g_wsq + k0 + 1);
            #pragma unroll
            for (int i = 0; i < 8; i++) {
                float s0, s1;
                unpack2(acc[i][j2], s0, s1);
                float v0 = __fsub_rn(__fadd_rn(zq[i], w0), 2.0f * s0);
                float v1 = __fsub_rn(__fadd_rn(zq[i], w1), 2.0f * s1);
                if (v0 < bestV[i]) { bestV[i] = v0; bestI[i] = k0; }
                if (v1 < bestV[i]) { bestV[i] = v1; bestI[i] = k0 + 1; }
            }
        }
    }

    // cross-thread (over tn) reduce: min value, lowest index on ties (compare indices!)
    __syncthreads();
    float* rv = sm;
    int* ri = (int*)(sm + 2048);
    #pragma unroll
    for (int i = 0; i < 8; i++) { rv[tid * 8 + i] = bestV[i]; ri[tid * 8 + i] = bestI[i]; }
    __syncthreads();
    if (tn == 0) {
        #pragma unroll
        for (int i = 0; i < 8; i++) {
            float bv = rv[(tm * 16) * 8 + i];
            int bi = ri[(tm * 16) * 8 + i];
            for (int t = 1; t < 16; t++) {
                float v = rv[(tm * 16 + t) * 8 + i];
                int id = ri[(tm * 16 + t) * 8 + i];
                if (v < bv || (v == bv && id < bi)) { bv = v; bi = id; }
            }
            g_token[gm0 + tm * 8 + i] = bi;
        }
    }
}

// ---------------- EMA / stats / output kernels ----------------
__global__ void k_scatter() {
    int n = blockIdx.x;
    int t = g_token[n];
    if (threadIdx.x == 0) atomicAdd(&g_counts[t], 1.0f);
    const float* src = g_zf + n * DDIM;
    float* dst = g_esum + t * DDIM;
    for (int d = threadIdx.x; d < DDIM; d += blockDim.x)
        atomicAdd(&dst[d], src[d]);
}

__global__ void k_cluster(const float* __restrict__ cs, float* __restrict__ ocn) {
    int k = blockIdx.x * 256 + threadIdx.x;
    float cnt = g_counts[k];
    float cn = 0.8f * cs[k] + 0.2f * cnt;
    ocn[k] = cn;
    float nz = (cnt > 0.f) ? 1.f : 0.f;
    float s_cn = cn, s_cnt = cnt, s_nz = nz;
    #pragma unroll
    for (int o = 16; o > 0; o >>= 1) {
        s_cn  += __shfl_down_sync(0xffffffffu, s_cn, o);
        s_cnt += __shfl_down_sync(0xffffffffu, s_cnt, o);
        s_nz  += __shfl_down_sync(0xffffffffu, s_nz, o);
    }
    if ((threadIdx.x & 31) == 0) {
        atomicAdd(&g_scal[1], s_cn);
        atomicAdd(&g_scal[2], s_cnt);
        atomicAdd(&g_scal[3], s_nz);
    }
}

__global__ void k_ema(const float* __restrict__ ea, float* __restrict__ oea) {
    int i = blockIdx.x * 256 + threadIdx.x;
    oea[i] = 0.8f * ea[i] + 0.2f * g_esum[i];
}

__global__ void k_entropy() {
    int k = blockIdx.x * 256 + threadIdx.x;
    float cnt = g_counts[k];
    float sumc = g_scal[2];
    float p = cnt / sumc;
    float term = p * logf(p + 1e-10f);
    #pragma unroll
    for (int o = 16; o > 0; o >>= 1) term += __shfl_down_sync(0xffffffffu, term, o);
    if ((threadIdx.x & 31) == 0) atomicAdd(&g_scal[4], term);
}

__global__ void k_weight(const float* __restrict__ ocn, const float* __restrict__ oea,
                         float* __restrict__ ow) {
    int i = blockIdx.x * 256 + threadIdx.x;
    int k = i >> 8;
    float cn = ocn[k];
    float n = g_scal[1];
    float t = (cn + 1e-5f) / (n + 0.16384f);   // K*EPS = 16384*1e-5
    float smv = t * n;
    ow[i] = oea[i] / smv;
}

__global__ void k_outloss(const float* __restrict__ z, const float* __restrict__ w,
                          float* __restrict__ oout) {
    int idx = blockIdx.x * 256 + threadIdx.x;
    int b = idx >> 18;
    int c = (idx >> 10) & 255;
    int p = idx & 1023;
    int n = (b << 10) | p;
    float zt = z[idx];
    float zqv = __ldg(&w[g_token[n] * DDIM + c]);
    float diff = __fsub_rn(zqv, zt);            // replicate (z_q - zt) rounding
    oout[idx] = __fadd_rn(zt, diff);            // replicate STE rounding exactly
    float sq = diff * diff;
    sq = blockReduceSum(sq);
    if (threadIdx.x == 0) atomicAdd(&g_scal[0], sq);
}

__global__ void k_scalars(float* __restrict__ o) {
    float S = g_scal[0];
    o[0] = 0.25f * (S / 4194304.0f);    // loss = BETA * mean
    o[1] = S / 16384.0f;                // quant_error
    o[2] = g_scal[3] / 16384.0f;        // utilization
    o[3] = expf(-g_scal[4]);            // perplexity
}

// ---------------- launch ----------------
extern "C" void kernel_launch(void* const* d_in, const int* in_sizes, int n_in,
                              void* d_out, int out_size) {
    const float* z  = (const float*)d_in[0];   // [16,256,32,32]
    const float* w  = (const float*)d_in[1];   // [16384,256]
    const float* cs = (const float*)d_in[2];   // [16384]
    const float* ea = (const float*)d_in[3];   // [16384,256]
    float* out = (float*)d_out;

    float* o_out  = out + O_OUT;
    float* o_scal = out + O_SCAL;
    float* o_wnew = out + O_WNEW;
    float* o_cnew = out + O_CNEW;
    float* o_ea   = out + O_EANEW;

    cudaFuncSetAttribute(k_gemm, cudaFuncAttributeMaxDynamicSharedMemorySize, GEMM_SMEM);

    k_zero<<<(KCB * DDIM + 255) / 256, 256>>>();
    k_zT<<<dim3(NBATCH, DDIM), 256>>>(z);
    k_zf<<<dim3(32, 8, NBATCH), dim3(32, 8)>>>(z);
    k_wT<<<dim3(8, 512), dim3(32, 8)>>>(w);
    k_zsq<<<N_TOK, 256>>>();
    k_wsq<<<KCB, 256>>>(w);
    k_gemm<<<N_TOK / TM, 256, GEMM_SMEM>>>();
    k_scatter<<<N_TOK, 128>>>();
    k_cluster<<<KCB / 256, 256>>>(cs, o_cnew);
    k_ema<<<(KCB * DDIM) / 256, 256>>>(ea, o_ea);
    k_entropy<<<KCB / 256, 256>>>();
    k_weight<<<(KCB * DDIM) / 256, 256>>>(o_cnew, o_ea, o_wnew);
    k_outloss<<<(NBATCH * DDIM * HWD) / 256, 256>>>(z, w, o_out);
    k_scalars<<<1, 1>>>(o_scal);
}